// round 17
// baseline (speedup 1.0000x reference)
#include <cuda_runtime.h>
#include <cstdint>
#include <math.h>

#define Bnum 32
#define Tnum 2048
#define Hnum 512
#define ROW4 (Hnum / 4)             // 128 float4 per row
#define ETHR 256                    // 8 warps
#define NPROJ 256                   // proj-role blocks (32 b x 8 h-slices)
#define DENSE_MIN 20                // >=20/32 live -> read full 64KB span

// Scratch (static device arrays — allocation-free per harness rules)
__device__ __align__(16) float g_has[Bnum * Hnum];   // ha (unscaled)
__device__ __align__(16) float g_p[Bnum * Tnum];     // unnormalized numerators
__device__ unsigned g_done[Bnum];     // per-b row-completion counters
__device__ unsigned g_pdone_all;      // proj slice counter
__device__ unsigned g_allready;       // proj done flag
__device__ unsigned g_nb;             // normalized-b counter

__device__ __forceinline__ float ex2a(float x) {
    float y; asm("ex2.approx.f32 %0, %1;" : "=f"(y) : "f"(x)); return y;
}
__device__ __forceinline__ float tanha(float x) {
    float y; asm("tanh.approx.f32 %0, %1;" : "=f"(y) : "f"(x)); return y;
}

#define LOG2E 1.4426950408889634f

// ---------------------------------------------------------------------------
// ONE kernel, block = one t row x all 32 b (contiguous 64KB span).
// Phase P (t<256): compute ha slice, release global ready flag.
// Phase S: hybrid dense/sparse row reads; per-b counters trigger in-kernel
// normalization of b by whichever block completes it (deterministic sums).
// ---------------------------------------------------------------------------
__global__ __launch_bounds__(ETHR, 6) void fused_kernel(
    const float* __restrict__ hidden,    // [2,B,H]
    const float* __restrict__ eo,        // [T,B,H]
    const int*   __restrict__ enc_len_w, // [B] int32/int64 (auto-detect)
    const float* __restrict__ Wh,        // [H,H]
    const float* __restrict__ bh,        // [H]
    const float* __restrict__ Wo,        // [1,H]
    float* __restrict__ out)             // [B,T,1]
{
    const int tid  = threadIdx.x;
    const int warp = tid >> 5;
    const int lane = tid & 31;
    const int t    = blockIdx.x;                  // 0..2047

    __shared__ __align__(16) float s_hm[Hnum];
    __shared__ float s_red[8];
    __shared__ float s_rinv;
    __shared__ unsigned s_fin;

    // ================= Phase P: projection (t < 256) ========================
    if (t < NPROJ) {
        const int pb = t >> 3;                    // 0..31
        const int h0 = (t & 7) * 64;              // 0,64,...,448
        if (tid < ROW4) {
            float4 a = ((const float4*)(hidden + (size_t)pb * Hnum))[tid];
            float4 c = ((const float4*)(hidden + (size_t)(Bnum + pb) * Hnum))[tid];
            float4 r;
            r.x = 0.5f * (a.x + c.x); r.y = 0.5f * (a.y + c.y);
            r.z = 0.5f * (a.z + c.z); r.w = 0.5f * (a.w + c.w);
            ((float4*)s_hm)[tid] = r;
        }
        __syncthreads();
        #pragma unroll
        for (int it = 0; it < 8; it++) {
            const int h = h0 + it * 8 + warp;
            const float4* __restrict__ w4 = (const float4*)(Wh + (size_t)h * Hnum);
            float acc = 0.f;
            #pragma unroll
            for (int i = 0; i < 4; i++) {
                const int k = i * 32 + lane;
                float4 w = w4[k];
                float4 m = ((const float4*)s_hm)[k];
                acc = fmaf(m.x, w.x, acc);
                acc = fmaf(m.y, w.y, acc);
                acc = fmaf(m.z, w.z, acc);
                acc = fmaf(m.w, w.w, acc);
            }
            #pragma unroll
            for (int off = 16; off; off >>= 1)
                acc += __shfl_xor_sync(0xffffffffu, acc, off);
            if (lane == 0)
                g_has[pb * Hnum + h] = acc + bh[h];
        }
        __threadfence();                          // publish g_has slice
        __syncthreads();
        if (tid == 0) {
            if (atomicAdd(&g_pdone_all, 1u) == NPROJ - 1u)
                atomicExch(&g_allready, 1u);
        }
    }

    // ===================== Phase S: energy streaming ========================
    // enc_len dtype auto-detect (JAX may canonicalize int64->int32):
    // lengths >= 1, so word[1]==0 iff buffer is little-endian int64.
    const bool is64 = (enc_len_w[1] == 0);
    const int len_l = is64 ? enc_len_w[2 * lane] : enc_len_w[lane];  // lane=b
    const unsigned livemask = __ballot_sync(0xffffffffu, t < len_l);
    const int nlive = __popc(livemask);
    if (nlive == 0) return;                       // fully dead row: retire

    if (tid == 0) {                               // wait for all ha slices
        while (atomicAdd(&g_allready, 0u) == 0u) __nanosleep(128);
        s_fin = 0u;
    }
    __syncthreads();

    const bool dense = (nlive >= DENSE_MIN);      // hybrid read policy
    const float4* __restrict__ eo4 = (const float4*)eo;
    const float4* __restrict__ wo4 = (const float4*)Wo;

    #pragma unroll
    for (int r = 0; r < 4; r++) {                 // warp covers b = 4w..4w+3
        const int b = warp * 4 + r;
        const int len_b = __shfl_sync(0xffffffffu, len_l, b);
        const bool live = (t < len_b);
        if (live || dense) {                      // dense: load even if masked
            const float4* __restrict__ ha4 = (const float4*)(g_has + b * Hnum);
            const size_t base = ((size_t)t * Bnum + b) * ROW4 + lane;
            float acc = 0.f;
            #pragma unroll
            for (int j = 0; j < 4; j++) {
                const int k = j * 32 + lane;
                float4 e  = __ldcs(&eo4[base + (size_t)j * 32]);
                float4 hs = __ldg(&ha4[k]);       // L1-resident (64KB total)
                float4 w  = __ldg(&wo4[k]);
                acc = fmaf(tanha(e.x + hs.x), w.x, acc);
                acc = fmaf(tanha(e.y + hs.y), w.y, acc);
                acc = fmaf(tanha(e.z + hs.z), w.z, acc);
                acc = fmaf(tanha(e.w + hs.w), w.w, acc);
            }
            #pragma unroll
            for (int off = 16; off; off >>= 1)
                acc += __shfl_xor_sync(0xffffffffu, acc, off);
            if (lane == 0 && live) {
                // no-max exp is safe: |energy| <= sum|Wo| ~ 18 << fp32 range
                float pv = ex2a(acc * LOG2E);
                g_p[b * Tnum + t] = pv;
                __threadfence();
                unsigned old = atomicAdd(&g_done[b], 1u);
                if (old + 1u == (unsigned)len_b)  // this block completed b
                    atomicOr(&s_fin, 1u << b);
            }
        }
    }
    __syncthreads();
    unsigned fin = s_fin;
    if (fin == 0u) return;

    // ---- normalize each b this block completed (deterministic sums) -------
    while (fin) {
        const int b = __ffs((int)fin) - 1;
        fin &= fin - 1u;
        const int len_b = is64 ? enc_len_w[2 * b] : enc_len_w[b];

        __syncthreads();                          // guard s_red reuse
        float v = 0.f;
        for (int q = tid; q < Tnum; q += ETHR)
            if (q < len_b) v += g_p[b * Tnum + q];
        #pragma unroll
        for (int off = 16; off; off >>= 1)
            v += __shfl_xor_sync(0xffffffffu, v, off);
        if (lane == 0) s_red[warp] = v;
        __syncthreads();
        if (tid == 0) {
            float tot = 0.f;
            #pragma unroll
            for (int k = 0; k < 8; k++) tot += s_red[k];
            s_rinv = 1.0f / tot;
        }
        __syncthreads();
        const float rinv = s_rinv;

        const float* __restrict__ prow = &g_p[b * Tnum];
        float4* __restrict__ o4 = (float4*)&out[b * Tnum];
        for (int q = tid; q < Tnum / 4; q += ETHR) {
            const int t0 = q * 4;
            float4 o = make_float4(0.f, 0.f, 0.f, 0.f);
            if (t0 + 3 < len_b) {
                float4 pv = ((const float4*)prow)[q];
                o.x = pv.x * rinv; o.y = pv.y * rinv;
                o.z = pv.z * rinv; o.w = pv.w * rinv;
            } else if (t0 < len_b) {
                if (t0 + 0 < len_b) o.x = prow[t0 + 0] * rinv;
                if (t0 + 1 < len_b) o.y = prow[t0 + 1] * rinv;
                if (t0 + 2 < len_b) o.z = prow[t0 + 2] * rinv;
                if (t0 + 3 < len_b) o.w = prow[t0 + 3] * rinv;
            }
            o4[q] = o;
        }
        if (tid == 0) {                           // reset for next graph replay
            g_done[b] = 0u;
            if (atomicAdd(&g_nb, 1u) == Bnum - 1u) {
                atomicExch(&g_allready, 0u);
                atomicExch(&g_pdone_all, 0u);
                atomicExch(&g_nb, 0u);
            }
        }
    }
}

// ---------------------------------------------------------------------------
extern "C" void kernel_launch(void* const* d_in, const int* in_sizes, int n_in,
                              void* d_out, int out_size)
{
    const float* hidden  = (const float*)d_in[0];      // [L,B,H]
    const float* eo      = (const float*)d_in[1];      // [T,B,H]
    const int*   enc_len = (const int*)d_in[2];        // [B] int32/int64 (auto-detect)
    const float* Wh      = (const float*)d_in[3];      // [H,H]
    const float* bh      = (const float*)d_in[4];      // [H]
    const float* Wo      = (const float*)d_in[5];      // [1,H]
    // d_in[6] = bo: uniform additive constant -> cancels in softmax, unused.
    float* out = (float*)d_out;                         // [B,T,1]

    fused_kernel<<<Tnum, ETHR>>>(hidden, eo, enc_len, Wh, bh, Wo, out);
}